// round 4
// baseline (speedup 1.0000x reference)
#include <cuda_runtime.h>
#include <math.h>

// ---------------- problem constants ----------------
#define NQ      32768      // BATCH*2 query rows
#define D       128        // embed dim
#define G4      1024       // gates width (8*d... actually 4*2d)
#define FEW     5

// ---------------- scratch (static device arrays; no allocation) ----------------
__device__ float d_SG[FEW * D];                 // support_g (5 x 128)
__device__ float d_S2[FEW * G4];                // support_g @ W_hh[:,128:].T  (5 x 1024)
__device__ float d_MS[D];                       // mean_support
__device__ float d_q   [(size_t)NQ * D];        // gathered query embeddings
__device__ float d_Gbuf[(size_t)NQ * 2048];     // cols 0..1023: G0 = q@Wih.T+b ; 1024..2047: G01 = q@(Wih+W1).T+b
__device__ float d_gates[(size_t)NQ * G4];      // per-step gates scratch
__device__ float d_c   [(size_t)NQ * 256];      // LSTM cell state
__device__ float d_hl  [(size_t)NQ * D];        // h_lstm[:, :128]
__device__ float d_attn[(size_t)NQ * 8];        // attention weights (5, padded to 8)
__device__ float d_Wbig[2048 * D];              // [W_ih ; W_ih + W_hh[:, :128]]
__device__ float d_bsum[G4];                    // b_ih + b_hh

__device__ __forceinline__ float sigf(float x) { return 1.0f / (1.0f + expf(-x)); }

// ---------------- tiny prep: Wbig / bsum ----------------
__global__ void k_wsum(const float* __restrict__ Wih, const float* __restrict__ Whh,
                       const float* __restrict__ bih, const float* __restrict__ bhh) {
    int idx = blockIdx.x * 256 + threadIdx.x;           // 2048*128 = 262144 total
    int r = idx >> 7, k = idx & 127;
    float v;
    if (r < 1024) v = Wih[idx];
    else          v = Wih[(size_t)(r - 1024) * 128 + k] + Whh[(size_t)(r - 1024) * 256 + k];
    d_Wbig[idx] = v;
    if (idx < 1024) d_bsum[idx] = bih[idx] + bhh[idx];
}

// ---------------- support path: GCN (linear!) + MLP + LayerNorm ----------------
__global__ void k_support(const int* __restrict__ sp, const float* __restrict__ emb,
                          const float* __restrict__ gW, const float* __restrict__ gb,
                          const float* __restrict__ p1W, const float* __restrict__ p1b,
                          const float* __restrict__ p2W, const float* __restrict__ p2b,
                          const float* __restrict__ lng, const float* __restrict__ lnb) {
    __shared__ float cs[256], s[128], h1[256], x[128], stat[2];
    int f = blockIdx.x, t = threadIdx.x;
    int side = t >> 7, col = t & 127;
    const int* pf = sp + f * 400;
    float acc = 0.f;
    #pragma unroll 4
    for (int n = 0; n < 200; n++) {
        int idx = pf[n * 2 + side];
        acc += emb[(size_t)idx * 128 + col];
    }
    cs[t] = acc;
    __syncthreads();
    if (t < 128) {                                   // support = tanh((csum@W.T + 200 b)/5)
        float a = 200.f * gb[t];
        #pragma unroll 4
        for (int k = 0; k < 256; k++) a = fmaf(cs[k], gW[t * 256 + k], a);
        s[t] = tanhf(a * 0.2f);
    }
    __syncthreads();
    {                                                // h1 = relu(s @ proj1_W.T + b1)
        float a = p1b[t];
        #pragma unroll 4
        for (int j = 0; j < 128; j++) a = fmaf(s[j], p1W[t * 128 + j], a);
        h1[t] = fmaxf(a, 0.f);
    }
    __syncthreads();
    if (t < 128) {                                   // x = h1 @ proj2_W.T + b2 + s
        float a = p2b[t];
        #pragma unroll 4
        for (int k = 0; k < 256; k++) a = fmaf(h1[k], p2W[t * 256 + k], a);
        x[t] = a + s[t];
    }
    __syncthreads();
    if (t == 0) {                                    // LayerNorm stats
        float mu = 0.f;
        for (int j = 0; j < 128; j++) mu += x[j];
        mu *= (1.f / 128.f);
        float v = 0.f;
        for (int j = 0; j < 128; j++) { float dd = x[j] - mu; v += dd * dd; }
        v *= (1.f / 128.f);
        stat[0] = mu; stat[1] = rsqrtf(v + 1e-5f);
    }
    __syncthreads();
    if (t < 128) d_SG[f * 128 + t] = lng[t] * (x[t] - stat[0]) * stat[1] + lnb[t];
}

// ---------------- S2 = SG @ W_hh[:,128:].T  and mean_support ----------------
__global__ void k_s2mean(const float* __restrict__ Whh) {
    __shared__ float sg[128];
    int b = blockIdx.x, t = threadIdx.x;             // block 128
    if (b < 40) {
        int f = b >> 3, gbk = b & 7;
        sg[t] = d_SG[f * 128 + t];
        __syncthreads();
        int g = gbk * 128 + t;
        float a = 0.f;
        #pragma unroll 4
        for (int j = 0; j < 128; j++) a = fmaf(sg[j], Whh[(size_t)g * 256 + 128 + j], a);
        d_S2[f * G4 + g] = a;
    } else {
        float a = 0.f;
        #pragma unroll
        for (int f = 0; f < FEW; f++) a += d_SG[f * 128 + t];
        d_MS[t] = a * 0.2f;
    }
}

// ---------------- gather q = emb[query_pairs] ----------------
__global__ void k_gather(const int* __restrict__ qp, const float* __restrict__ emb) {
    int row = blockIdx.x * 8 + (threadIdx.x >> 5);
    int lane = threadIdx.x & 31;
    int idx = qp[row];
    float4 v = *(const float4*)(emb + (size_t)idx * 128 + lane * 4);
    *(float4*)(d_q + (size_t)row * 128 + lane * 4) = v;
}

// ---------------- SGEMM tiling params ----------------
#define GBM 128
#define GBN 64
#define GBK 32
#define PA  132
#define PB  68

// GEMM1: Gbuf = q(32768x128) @ Wbig.T(128x2048) + bsum
__global__ void __launch_bounds__(256) k_gemm1() {
    __shared__ float As[GBK * PA];
    __shared__ float Bs[GBK * PB];
    int tid = threadIdx.x;
    int bx = blockIdx.x, by = blockIdx.y;
    const float* Ag = d_q   + (size_t)by * GBM * 128;
    const float* Bg = d_Wbig + (size_t)bx * GBN * 128;
    int tx = tid & 15, ty = tid >> 4;
    float acc[8][4];
    #pragma unroll
    for (int m = 0; m < 8; m++)
        #pragma unroll
        for (int n = 0; n < 4; n++) acc[m][n] = 0.f;

    for (int kc = 0; kc < 4; kc++) {
        #pragma unroll
        for (int i = 0; i < 4; i++) {
            int lin = (tid + i * 256) << 2;
            int r = lin >> 5, k0 = lin & 31;
            float4 v = *(const float4*)(Ag + r * 128 + kc * 32 + k0);
            As[(k0 + 0) * PA + r] = v.x; As[(k0 + 1) * PA + r] = v.y;
            As[(k0 + 2) * PA + r] = v.z; As[(k0 + 3) * PA + r] = v.w;
        }
        #pragma unroll
        for (int i = 0; i < 2; i++) {
            int lin = (tid + i * 256) << 2;
            int n = lin >> 5, k0 = lin & 31;
            float4 v = *(const float4*)(Bg + n * 128 + kc * 32 + k0);
            Bs[(k0 + 0) * PB + n] = v.x; Bs[(k0 + 1) * PB + n] = v.y;
            Bs[(k0 + 2) * PB + n] = v.z; Bs[(k0 + 3) * PB + n] = v.w;
        }
        __syncthreads();
        #pragma unroll 8
        for (int k = 0; k < GBK; k++) {
            float4 a0 = *(const float4*)(As + k * PA + ty * 8);
            float4 a1 = *(const float4*)(As + k * PA + ty * 8 + 4);
            float4 b4 = *(const float4*)(Bs + k * PB + tx * 4);
            float av[8] = {a0.x, a0.y, a0.z, a0.w, a1.x, a1.y, a1.z, a1.w};
            float bv[4] = {b4.x, b4.y, b4.z, b4.w};
            #pragma unroll
            for (int m = 0; m < 8; m++)
                #pragma unroll
                for (int n = 0; n < 4; n++)
                    acc[m][n] = fmaf(av[m], bv[n], acc[m][n]);
        }
        __syncthreads();
    }
    int col0 = bx * GBN + tx * 4;
    float4 bv4 = *(const float4*)(d_bsum + (col0 & 1023));
    #pragma unroll
    for (int m = 0; m < 8; m++) {
        int row = by * GBM + ty * 8 + m;
        float4 o;
        o.x = acc[m][0] + bv4.x; o.y = acc[m][1] + bv4.y;
        o.z = acc[m][2] + bv4.z; o.w = acc[m][3] + bv4.w;
        *(float4*)(d_Gbuf + (size_t)row * 2048 + col0) = o;
    }
}

// GEMM2: gates = hl @ W1.T + G01 + attn @ S2   (W1 = W_hh[:, :128])
// last=1: only gate columns {q*256 + j, j<128} computed, packed into Nw=512
__global__ void __launch_bounds__(256) k_gemm2(const float* __restrict__ Whh, int last, int Nw) {
    __shared__ float As[GBK * PA];
    __shared__ float Bs[GBK * PB];
    int tid = threadIdx.x;
    int bx = blockIdx.x, by = blockIdx.y;
    int colblk = bx * GBN;
    int gb0 = last ? (((colblk >> 7) << 8) + (colblk & 127)) : colblk;
    const float* Ag = d_hl + (size_t)by * GBM * 128;
    const float* Bg = Whh + (size_t)gb0 * 256;
    int tx = tid & 15, ty = tid >> 4;
    float acc[8][4];
    #pragma unroll
    for (int m = 0; m < 8; m++)
        #pragma unroll
        for (int n = 0; n < 4; n++) acc[m][n] = 0.f;

    for (int kc = 0; kc < 4; kc++) {
        #pragma unroll
        for (int i = 0; i < 4; i++) {
            int lin = (tid + i * 256) << 2;
            int r = lin >> 5, k0 = lin & 31;
            float4 v = *(const float4*)(Ag + r * 128 + kc * 32 + k0);
            As[(k0 + 0) * PA + r] = v.x; As[(k0 + 1) * PA + r] = v.y;
            As[(k0 + 2) * PA + r] = v.z; As[(k0 + 3) * PA + r] = v.w;
        }
        #pragma unroll
        for (int i = 0; i < 2; i++) {
            int lin = (tid + i * 256) << 2;
            int n = lin >> 5, k0 = lin & 31;
            float4 v = *(const float4*)(Bg + (size_t)n * 256 + kc * 32 + k0);
            Bs[(k0 + 0) * PB + n] = v.x; Bs[(k0 + 1) * PB + n] = v.y;
            Bs[(k0 + 2) * PB + n] = v.z; Bs[(k0 + 3) * PB + n] = v.w;
        }
        __syncthreads();
        #pragma unroll 8
        for (int k = 0; k < GBK; k++) {
            float4 a0 = *(const float4*)(As + k * PA + ty * 8);
            float4 a1 = *(const float4*)(As + k * PA + ty * 8 + 4);
            float4 b4 = *(const float4*)(Bs + k * PB + tx * 4);
            float av[8] = {a0.x, a0.y, a0.z, a0.w, a1.x, a1.y, a1.z, a1.w};
            float bv[4] = {b4.x, b4.y, b4.z, b4.w};
            #pragma unroll
            for (int m = 0; m < 8; m++)
                #pragma unroll
                for (int n = 0; n < 4; n++)
                    acc[m][n] = fmaf(av[m], bv[n], acc[m][n]);
        }
        __syncthreads();
    }
    int gcol = gb0 + tx * 4;
    float4 s2v[FEW];
    #pragma unroll
    for (int f = 0; f < FEW; f++) s2v[f] = *(const float4*)(d_S2 + f * G4 + gcol);
    #pragma unroll
    for (int m = 0; m < 8; m++) {
        int row = by * GBM + ty * 8 + m;
        float4 o = *(const float4*)(d_Gbuf + (size_t)row * 2048 + 1024 + gcol);
        o.x += acc[m][0]; o.y += acc[m][1]; o.z += acc[m][2]; o.w += acc[m][3];
        #pragma unroll
        for (int f = 0; f < FEW; f++) {
            float av = d_attn[(size_t)row * 8 + f];
            o.x = fmaf(av, s2v[f].x, o.x);
            o.y = fmaf(av, s2v[f].y, o.y);
            o.z = fmaf(av, s2v[f].z, o.z);
            o.w = fmaf(av, s2v[f].w, o.w);
        }
        *(float4*)(d_gates + (size_t)row * Nw + colblk + tx * 4) = o;
    }
}

// ---------------- elementwise LSTM update + attention softmax ----------------
__global__ void __launch_bounds__(256) k_lstm(int first) {
    __shared__ float sSg[FEW * 128];
    for (int i = threadIdx.x; i < FEW * 128; i += 256) sSg[i] = d_SG[i];
    __syncthreads();
    int row = blockIdx.x * 8 + (threadIdx.x >> 5);
    int lane = threadIdx.x & 31;
    const float* gr = (first ? d_Gbuf : d_gates) + (size_t)row * (first ? 2048 : 1024);
    float part[FEW] = {0.f, 0.f, 0.f, 0.f, 0.f};
    #pragma unroll
    for (int k = 0; k < 8; k++) {
        int j = lane + 32 * k;
        float gi = gr[j], gf = gr[256 + j], gg = gr[512 + j], go = gr[768 + j];
        float co = first ? 0.f : d_c[(size_t)row * 256 + j];
        float cn = fmaf(sigf(gf), co, sigf(gi) * tanhf(gg));
        d_c[(size_t)row * 256 + j] = cn;
        if (k < 4) {
            float hl = sigf(go) * tanhf(cn);
            float hq = d_q[(size_t)row * 128 + j] + hl;
            d_hl[(size_t)row * 128 + j] = hl;
            #pragma unroll
            for (int f = 0; f < FEW; f++) part[f] = fmaf(hq, sSg[f * 128 + j], part[f]);
        }
    }
    #pragma unroll
    for (int o = 16; o; o >>= 1)
        #pragma unroll
        for (int f = 0; f < FEW; f++) part[f] += __shfl_xor_sync(0xffffffffu, part[f], o);
    if (lane == 0) {
        float m = part[0];
        #pragma unroll
        for (int f = 1; f < FEW; f++) m = fmaxf(m, part[f]);
        float e[FEW], ss = 0.f;
        #pragma unroll
        for (int f = 0; f < FEW; f++) { e[f] = expf(part[f] - m); ss += e[f]; }
        float inv = 1.f / ss;
        #pragma unroll
        for (int f = 0; f < FEW; f++) d_attn[(size_t)row * 8 + f] = e[f] * inv;
    }
}

// last step: packed 512-wide gates, only c[:128]/hl needed, no attention
__global__ void __launch_bounds__(256) k_lstm_last() {
    int row = blockIdx.x * 8 + (threadIdx.x >> 5);
    int lane = threadIdx.x & 31;
    const float* gr = d_gates + (size_t)row * 512;
    #pragma unroll
    for (int k = 0; k < 4; k++) {
        int j = lane + 32 * k;
        float gi = gr[j], gf = gr[128 + j], gg = gr[256 + j], go = gr[384 + j];
        float co = d_c[(size_t)row * 256 + j];
        float cn = fmaf(sigf(gf), co, sigf(gi) * tanhf(gg));
        float hl = sigf(go) * tanhf(cn);
        d_hl[(size_t)row * 128 + j] = hl;
    }
}

// ---------------- final: out[b] = mean(hq[2b], hq[2b+1]) . mean_support ----------------
__global__ void k_final(float* __restrict__ out) {
    __shared__ float ms[128];
    int t = threadIdx.x;
    if (t < 128) ms[t] = d_MS[t];
    __syncthreads();
    int b = blockIdx.x * 8 + (t >> 5);
    int lane = t & 31;
    const float* q0 = d_q  + (size_t)b * 256;
    const float* h0 = d_hl + (size_t)b * 256;
    int j = lane * 4;
    float4 qa = *(const float4*)(q0 + j);
    float4 qb = *(const float4*)(q0 + 128 + j);
    float4 ha = *(const float4*)(h0 + j);
    float4 hb = *(const float4*)(h0 + 128 + j);
    float4 m4 = *(const float4*)(ms + j);
    float p = 0.5f * ((qa.x + ha.x + qb.x + hb.x) * m4.x +
                      (qa.y + ha.y + qb.y + hb.y) * m4.y +
                      (qa.z + ha.z + qb.z + hb.z) * m4.z +
                      (qa.w + ha.w + qb.w + hb.w) * m4.w);
    #pragma unroll
    for (int o = 16; o; o >>= 1) p += __shfl_xor_sync(0xffffffffu, p, o);
    if (lane == 0) out[b] = p;
}

// ---------------- launcher ----------------
extern "C" void kernel_launch(void* const* d_in, const int* in_sizes, int n_in,
                              void* d_out, int out_size) {
    const int*   qp  = (const int*)d_in[0];
    const int*   sp  = (const int*)d_in[1];
    const float* emb = (const float*)d_in[2];
    const float* gW  = (const float*)d_in[3];
    const float* gb  = (const float*)d_in[4];
    const float* p1W = (const float*)d_in[5];
    const float* p1b = (const float*)d_in[6];
    const float* p2W = (const float*)d_in[7];
    const float* p2b = (const float*)d_in[8];
    const float* lng = (const float*)d_in[9];
    const float* lnb = (const float*)d_in[10];
    const float* Wih = (const float*)d_in[11];
    const float* Whh = (const float*)d_in[12];
    const float* bih = (const float*)d_in[13];
    const float* bhh = (const float*)d_in[14];
    float* out = (float*)d_out;

    k_wsum<<<1024, 256>>>(Wih, Whh, bih, bhh);
    k_support<<<5, 256>>>(sp, emb, gW, gb, p1W, p1b, p2W, p2b, lng, lnb);
    k_s2mean<<<41, 128>>>(Whh);
    k_gather<<<NQ / 8, 256>>>(qp, emb);

    // G0 / G01 precompute (q is loop-invariant)
    k_gemm1<<<dim3(2048 / GBN, NQ / GBM), 256>>>();

    // step 0: gates = G0
    k_lstm<<<NQ / 8, 256>>>(1);
    // steps 1,2
    for (int t = 0; t < 2; t++) {
        k_gemm2<<<dim3(1024 / GBN, NQ / GBM), 256>>>(Whh, 0, 1024);
        k_lstm<<<NQ / 8, 256>>>(0);
    }
    // step 3: half the gate columns, no attention
    k_gemm2<<<dim3(512 / GBN, NQ / GBM), 256>>>(Whh, 1, 512);
    k_lstm_last<<<NQ / 8, 256>>>();

    k_final<<<16384 / 8, 256>>>(out);
}

// round 5
// speedup vs baseline: 1.2880x; 1.2880x over previous
#include <cuda_runtime.h>
#include <math.h>

// ---------------- problem constants ----------------
#define NQ      32768      // BATCH*2 query rows
#define D       128        // embed dim
#define G4      1024       // gate width
#define FEW     5

// ---------------- scratch (static device arrays; no allocation) ----------------
__device__ float d_SG[FEW * D];                 // support_g (5 x 128)
__device__ float d_S2[FEW * G4];                // support_g @ W_hh[:,128:].T  (5 x 1024)
__device__ float d_MS[D];                       // mean_support
__device__ float d_q   [(size_t)NQ * D];        // gathered query embeddings
__device__ float d_Gbuf[(size_t)NQ * G4];       // G01 = q@(W_ih + W_hh[:,:128]).T + (b_ih+b_hh)
__device__ float d_gates[(size_t)NQ * G4];      // per-step gates scratch
__device__ float d_c   [(size_t)NQ * 256];      // LSTM cell state
__device__ float d_hl  [(size_t)NQ * D];        // h_lstm[:, :128]  (init: -q for step0 trick)
__device__ float d_attn[(size_t)NQ * 8];        // attention weights (5, padded to 8)
__device__ float d_Wcomb[G4 * D];               // W_ih + W_hh[:, :128]
__device__ float d_bsum[G4];                    // b_ih + b_hh

__device__ __forceinline__ float sigf(float x) { return 1.0f / (1.0f + expf(-x)); }

__device__ __forceinline__ unsigned f2tf(float x) {
    unsigned r;
    asm("cvt.rna.tf32.f32 %0, %1;" : "=r"(r) : "f"(x));
    return r;
}

__device__ __forceinline__ void mma_tf32(float* c, const unsigned* a, const unsigned* b) {
    asm volatile(
        "mma.sync.aligned.m16n8k8.row.col.f32.tf32.tf32.f32 "
        "{%0,%1,%2,%3}, {%4,%5,%6,%7}, {%8,%9}, {%0,%1,%2,%3};"
        : "+f"(c[0]), "+f"(c[1]), "+f"(c[2]), "+f"(c[3])
        : "r"(a[0]), "r"(a[1]), "r"(a[2]), "r"(a[3]), "r"(b[0]), "r"(b[1]));
}

// ---------------- tiny prep: Wcomb / bsum ----------------
__global__ void k_wsum(const float* __restrict__ Wih, const float* __restrict__ Whh,
                       const float* __restrict__ bih, const float* __restrict__ bhh) {
    int idx = blockIdx.x * 256 + threadIdx.x;           // 1024*128 = 131072
    int r = idx >> 7, k = idx & 127;
    d_Wcomb[idx] = Wih[idx] + Whh[(size_t)r * 256 + k];
    if (idx < 1024) d_bsum[idx] = bih[idx] + bhh[idx];
}

// ---------------- support path: GCN (linear!) + MLP + LayerNorm ----------------
__global__ void k_support(const int* __restrict__ sp, const float* __restrict__ emb,
                          const float* __restrict__ gW, const float* __restrict__ gb,
                          const float* __restrict__ p1W, const float* __restrict__ p1b,
                          const float* __restrict__ p2W, const float* __restrict__ p2b,
                          const float* __restrict__ lng, const float* __restrict__ lnb) {
    __shared__ float cs[256], s[128], h1[256], x[128], stat[2];
    int f = blockIdx.x, t = threadIdx.x;
    int side = t >> 7, col = t & 127;
    const int* pf = sp + f * 400;
    float acc = 0.f;
    #pragma unroll 4
    for (int n = 0; n < 200; n++) {
        int idx = pf[n * 2 + side];
        acc += emb[(size_t)idx * 128 + col];
    }
    cs[t] = acc;
    __syncthreads();
    if (t < 128) {                                   // support = tanh((csum@W.T + 200 b)/5)
        float a = 200.f * gb[t];
        #pragma unroll 4
        for (int k = 0; k < 256; k++) a = fmaf(cs[k], gW[t * 256 + k], a);
        s[t] = tanhf(a * 0.2f);
    }
    __syncthreads();
    {                                                // h1 = relu(s @ proj1_W.T + b1)
        float a = p1b[t];
        #pragma unroll 4
        for (int j = 0; j < 128; j++) a = fmaf(s[j], p1W[t * 128 + j], a);
        h1[t] = fmaxf(a, 0.f);
    }
    __syncthreads();
    if (t < 128) {                                   // x = h1 @ proj2_W.T + b2 + s
        float a = p2b[t];
        #pragma unroll 4
        for (int k = 0; k < 256; k++) a = fmaf(h1[k], p2W[t * 256 + k], a);
        x[t] = a + s[t];
    }
    __syncthreads();
    if (t == 0) {                                    // LayerNorm stats
        float mu = 0.f;
        for (int j = 0; j < 128; j++) mu += x[j];
        mu *= (1.f / 128.f);
        float v = 0.f;
        for (int j = 0; j < 128; j++) { float dd = x[j] - mu; v += dd * dd; }
        v *= (1.f / 128.f);
        stat[0] = mu; stat[1] = rsqrtf(v + 1e-5f);
    }
    __syncthreads();
    if (t < 128) d_SG[f * 128 + t] = lng[t] * (x[t] - stat[0]) * stat[1] + lnb[t];
}

// ---------------- S2 = SG @ W_hh[:,128:].T  and mean_support ----------------
__global__ void k_s2mean(const float* __restrict__ Whh) {
    __shared__ float sg[128];
    int b = blockIdx.x, t = threadIdx.x;             // block 128
    if (b < 40) {
        int f = b >> 3, gbk = b & 7;
        sg[t] = d_SG[f * 128 + t];
        __syncthreads();
        int g = gbk * 128 + t;
        float a = 0.f;
        #pragma unroll 4
        for (int j = 0; j < 128; j++) a = fmaf(sg[j], Whh[(size_t)g * 256 + 128 + j], a);
        d_S2[f * G4 + g] = a;
    } else {
        float a = 0.f;
        #pragma unroll
        for (int f = 0; f < FEW; f++) a += d_SG[f * 128 + t];
        d_MS[t] = a * 0.2f;
    }
}

// ---------------- gather q = emb[query_pairs]; hl init = -q (step-0 trick) ----------------
__global__ void k_gather(const int* __restrict__ qp, const float* __restrict__ emb) {
    int row = blockIdx.x * 8 + (threadIdx.x >> 5);
    int lane = threadIdx.x & 31;
    int idx = qp[row];
    float4 v = *(const float4*)(emb + (size_t)idx * 128 + lane * 4);
    *(float4*)(d_q + (size_t)row * 128 + lane * 4) = v;
    float4 nv = make_float4(-v.x, -v.y, -v.z, -v.w);
    *(float4*)(d_hl + (size_t)row * 128 + lane * 4) = nv;
}

// ---------------- tf32 tensor-core GEMM (M-tile 128, N-tile 64, K=128) ----------------
// mode 0: Gbuf = A @ B.T + bias            (A = q,  B = Wcomb, strideB=128)
// mode 1: gates = A @ B.T + Gbuf           (A = -q, B = Whh[:, :128], strideB=256)
// mode 2: gates = A @ B.T + Gbuf + attn@S2 (A = hl)
// last=1: gate columns remapped ((cb>>7)<<8)+(cb&127), output packed width Nw.
#define PADA 36
__global__ void __launch_bounds__(256) k_gemm_tc(const float* __restrict__ A,
                                                 const float* __restrict__ B,
                                                 int strideB, int mode, int last, int Nw,
                                                 const float* __restrict__ bias) {
    __shared__ float As[128 * PADA];   // 18 KB
    __shared__ float Bs[64 * PADA];    //  9 KB
    __shared__ float sS2[FEW * 64];
    __shared__ float sAttn[128 * FEW];

    int tid = threadIdx.x, lane = tid & 31, warp = tid >> 5;
    int wm = warp >> 1, wn = warp & 1;           // warps 4(M) x 2(N)
    int bx = blockIdx.x, by = blockIdx.y;
    int colblk = bx * 64;
    int gb0 = last ? (((colblk >> 7) << 8) + (colblk & 127)) : colblk;
    const float* Ag = A + (size_t)by * 128 * 128;
    const float* Bg = B + (size_t)gb0 * strideB;

    float acc[2][4][4];
    #pragma unroll
    for (int mi = 0; mi < 2; mi++)
        #pragma unroll
        for (int ni = 0; ni < 4; ni++)
            #pragma unroll
            for (int r = 0; r < 4; r++) acc[mi][ni][r] = 0.f;

    unsigned* Au = (unsigned*)As;
    unsigned* Bu = (unsigned*)Bs;

    for (int kc = 0; kc < 4; kc++) {
        // A tile: 128 x 32
        #pragma unroll
        for (int it = 0; it < 4; it++) {
            int lin = tid + it * 256;            // 0..1023
            int r = lin >> 3, c4 = (lin & 7) << 2;
            float4 v = *(const float4*)(Ag + r * 128 + kc * 32 + c4);
            uint4 u = make_uint4(f2tf(v.x), f2tf(v.y), f2tf(v.z), f2tf(v.w));
            *(uint4*)(Au + r * PADA + c4) = u;
        }
        // B tile: 64 x 32
        #pragma unroll
        for (int it = 0; it < 2; it++) {
            int lin = tid + it * 256;            // 0..511
            int r = lin >> 3, c4 = (lin & 7) << 2;
            float4 v = *(const float4*)(Bg + (size_t)r * strideB + kc * 32 + c4);
            uint4 u = make_uint4(f2tf(v.x), f2tf(v.y), f2tf(v.z), f2tf(v.w));
            *(uint4*)(Bu + r * PADA + c4) = u;
        }
        __syncthreads();

        #pragma unroll
        for (int k8 = 0; k8 < 4; k8++) {
            int kf = k8 * 8 + (lane & 3);
            unsigned a[2][4], b[4][2];
            int ar = wm * 32 + (lane >> 2);
            #pragma unroll
            for (int mi = 0; mi < 2; mi++) {
                const unsigned* p = Au + (ar + mi * 16) * PADA + kf;
                a[mi][0] = p[0];
                a[mi][1] = p[8 * PADA];
                a[mi][2] = p[4];
                a[mi][3] = p[8 * PADA + 4];
            }
            int br = wn * 32 + (lane >> 2);
            #pragma unroll
            for (int ni = 0; ni < 4; ni++) {
                const unsigned* p = Bu + (br + ni * 8) * PADA + kf;
                b[ni][0] = p[0];
                b[ni][1] = p[4];
            }
            #pragma unroll
            for (int mi = 0; mi < 2; mi++)
                #pragma unroll
                for (int ni = 0; ni < 4; ni++)
                    mma_tf32(acc[mi][ni], a[mi], b[ni]);
        }
        __syncthreads();
    }

    if (mode == 2) {
        for (int i = tid; i < FEW * 64; i += 256)
            sS2[i] = d_S2[(i >> 6) * G4 + gb0 + (i & 63)];
        for (int i = tid; i < 128 * FEW; i += 256) {
            int r = i / FEW, f = i - r * FEW;
            sAttn[i] = d_attn[((size_t)(by * 128 + r)) * 8 + f];
        }
        __syncthreads();
    }

    // epilogue
    #pragma unroll
    for (int mi = 0; mi < 2; mi++) {
        #pragma unroll
        for (int ni = 0; ni < 4; ni++) {
            int row0 = by * 128 + wm * 32 + mi * 16 + (lane >> 2);
            int cit = wn * 32 + ni * 8 + 2 * (lane & 3);
            if (mode == 0) {
                float2 bv = *(const float2*)(bias + colblk + cit);
                float2 o0 = make_float2(acc[mi][ni][0] + bv.x, acc[mi][ni][1] + bv.y);
                float2 o1 = make_float2(acc[mi][ni][2] + bv.x, acc[mi][ni][3] + bv.y);
                *(float2*)(d_Gbuf + (size_t)row0 * G4 + colblk + cit) = o0;
                *(float2*)(d_Gbuf + (size_t)(row0 + 8) * G4 + colblk + cit) = o1;
            } else {
                int gcol = gb0 + cit;
                #pragma unroll
                for (int rr = 0; rr < 2; rr++) {
                    int row = row0 + rr * 8;
                    float2 g = *(const float2*)(d_Gbuf + (size_t)row * G4 + gcol);
                    float x0 = acc[mi][ni][rr * 2 + 0] + g.x;
                    float x1 = acc[mi][ni][rr * 2 + 1] + g.y;
                    if (mode == 2) {
                        int lr = row - by * 128;
                        #pragma unroll
                        for (int f = 0; f < FEW; f++) {
                            float av = sAttn[lr * FEW + f];
                            x0 = fmaf(av, sS2[f * 64 + cit], x0);
                            x1 = fmaf(av, sS2[f * 64 + cit + 1], x1);
                        }
                    }
                    float2 o = make_float2(x0, x1);
                    *(float2*)(d_gates + (size_t)row * Nw + colblk + cit) = o;
                }
            }
        }
    }
}

// ---------------- elementwise LSTM update + attention softmax ----------------
__global__ void __launch_bounds__(256) k_lstm(int first) {
    __shared__ float sSg[FEW * 128];
    for (int i = threadIdx.x; i < FEW * 128; i += 256) sSg[i] = d_SG[i];
    __syncthreads();
    int row = blockIdx.x * 8 + (threadIdx.x >> 5);
    int lane = threadIdx.x & 31;
    const float* gr = d_gates + (size_t)row * 1024;
    float part[FEW] = {0.f, 0.f, 0.f, 0.f, 0.f};
    #pragma unroll
    for (int k = 0; k < 8; k++) {
        int j = lane + 32 * k;
        float gi = gr[j], gf = gr[256 + j], gg = gr[512 + j], go = gr[768 + j];
        float co = first ? 0.f : d_c[(size_t)row * 256 + j];
        float cn = fmaf(sigf(gf), co, sigf(gi) * tanhf(gg));
        d_c[(size_t)row * 256 + j] = cn;
        if (k < 4) {
            float hl = sigf(go) * tanhf(cn);
            float hq = d_q[(size_t)row * 128 + j] + hl;
            d_hl[(size_t)row * 128 + j] = hl;
            #pragma unroll
            for (int f = 0; f < FEW; f++) part[f] = fmaf(hq, sSg[f * 128 + j], part[f]);
        }
    }
    #pragma unroll
    for (int o = 16; o; o >>= 1)
        #pragma unroll
        for (int f = 0; f < FEW; f++) part[f] += __shfl_xor_sync(0xffffffffu, part[f], o);
    if (lane == 0) {
        float m = part[0];
        #pragma unroll
        for (int f = 1; f < FEW; f++) m = fmaxf(m, part[f]);
        float e[FEW], ss = 0.f;
        #pragma unroll
        for (int f = 0; f < FEW; f++) { e[f] = expf(part[f] - m); ss += e[f]; }
        float inv = 1.f / ss;
        #pragma unroll
        for (int f = 0; f < FEW; f++) d_attn[(size_t)row * 8 + f] = e[f] * inv;
    }
}

// last step: packed 512-wide gates, only c[:128]/hl needed, no attention
__global__ void __launch_bounds__(256) k_lstm_last() {
    int row = blockIdx.x * 8 + (threadIdx.x >> 5);
    int lane = threadIdx.x & 31;
    const float* gr = d_gates + (size_t)row * 512;
    #pragma unroll
    for (int k = 0; k < 4; k++) {
        int j = lane + 32 * k;
        float gi = gr[j], gf = gr[128 + j], gg = gr[256 + j], go = gr[384 + j];
        float co = d_c[(size_t)row * 256 + j];
        float cn = fmaf(sigf(gf), co, sigf(gi) * tanhf(gg));
        float hl = sigf(go) * tanhf(cn);
        d_hl[(size_t)row * 128 + j] = hl;
    }
}

// ---------------- final: out[b] = mean(hq[2b], hq[2b+1]) . mean_support ----------------
__global__ void k_final(float* __restrict__ out) {
    __shared__ float ms[128];
    int t = threadIdx.x;
    if (t < 128) ms[t] = d_MS[t];
    __syncthreads();
    int b = blockIdx.x * 8 + (t >> 5);
    int lane = t & 31;
    const float* q0 = d_q  + (size_t)b * 256;
    const float* h0 = d_hl + (size_t)b * 256;
    int j = lane * 4;
    float4 qa = *(const float4*)(q0 + j);
    float4 qb = *(const float4*)(q0 + 128 + j);
    float4 ha = *(const float4*)(h0 + j);
    float4 hb = *(const float4*)(h0 + 128 + j);
    float4 m4 = *(const float4*)(ms + j);
    float p = 0.5f * ((qa.x + ha.x + qb.x + hb.x) * m4.x +
                      (qa.y + ha.y + qb.y + hb.y) * m4.y +
                      (qa.z + ha.z + qb.z + hb.z) * m4.z +
                      (qa.w + ha.w + qb.w + hb.w) * m4.w);
    #pragma unroll
    for (int o = 16; o; o >>= 1) p += __shfl_xor_sync(0xffffffffu, p, o);
    if (lane == 0) out[b] = p;
}

// ---------------- launcher ----------------
extern "C" void kernel_launch(void* const* d_in, const int* in_sizes, int n_in,
                              void* d_out, int out_size) {
    const int*   qp  = (const int*)d_in[0];
    const int*   sp  = (const int*)d_in[1];
    const float* emb = (const float*)d_in[2];
    const float* gW  = (const float*)d_in[3];
    const float* gb  = (const float*)d_in[4];
    const float* p1W = (const float*)d_in[5];
    const float* p1b = (const float*)d_in[6];
    const float* p2W = (const float*)d_in[7];
    const float* p2b = (const float*)d_in[8];
    const float* lng = (const float*)d_in[9];
    const float* lnb = (const float*)d_in[10];
    const float* Wih = (const float*)d_in[11];
    const float* Whh = (const float*)d_in[12];
    const float* bih = (const float*)d_in[13];
    const float* bhh = (const float*)d_in[14];
    float* out = (float*)d_out;

    // device globals (valid to take addresses host-side only via symbols; use
    // kernels' internal references instead — pass raw pointers for A/B/bias)
    k_wsum<<<512, 256>>>(Wih, Whh, bih, bhh);
    k_support<<<5, 256>>>(sp, emb, gW, gb, p1W, p1b, p2W, p2b, lng, lnb);
    k_s2mean<<<41, 128>>>(Whh);
    k_gather<<<NQ / 8, 256>>>(qp, emb);

    float* pQ;     cudaGetSymbolAddress((void**)&pQ,     d_q);
    float* pHL;    cudaGetSymbolAddress((void**)&pHL,    d_hl);
    float* pWcomb; cudaGetSymbolAddress((void**)&pWcomb, d_Wcomb);
    float* pBsum;  cudaGetSymbolAddress((void**)&pBsum,  d_bsum);

    dim3 gFull(16, NQ / 128);   // N=1024
    dim3 gHalf(8,  NQ / 128);   // N=512 (last step)

    // G01 precompute (q is loop-invariant): Gbuf = q @ Wcomb.T + bsum
    k_gemm_tc<<<gFull, 256>>>(pQ, pWcomb, 128, 0, 0, G4, pBsum);

    // step 0: gates = G01 + (-q) @ W1.T  (== q@Wih.T + b)
    k_gemm_tc<<<gFull, 256>>>(pHL, Whh, 256, 1, 0, G4, pBsum);
    k_lstm<<<NQ / 8, 256>>>(1);

    // steps 1,2: gates = G01 + hl @ W1.T + attn @ S2
    for (int t = 0; t < 2; t++) {
        k_gemm_tc<<<gFull, 256>>>(pHL, Whh, 256, 2, 0, G4, pBsum);
        k_lstm<<<NQ / 8, 256>>>(0);
    }

    // step 3: half the gate columns, no attention output needed afterwards
    k_gemm_tc<<<gHalf, 256>>>(pHL, Whh, 256, 2, 1, 512, pBsum);
    k_lstm_last<<<NQ / 8, 256>>>();

    k_final<<<16384 / 8, 256>>>(out);
}

// round 6
// speedup vs baseline: 1.7188x; 1.3345x over previous
#include <cuda_runtime.h>
#include <cuda_fp16.h>
#include <math.h>

// ---------------- problem constants ----------------
#define NQ      32768      // BATCH*2 query rows
#define D       128        // embed dim
#define G4      1024       // gate width
#define FEW     5
#define SST     136        // smem stride (halfs): bank = (4r+tg)%32 -> conflict-free
#define SMEM_BYTES (2 * 128 * SST * 2)

// ---------------- scratch (static device arrays; no allocation) ----------------
__device__ float  d_SG[FEW * D];                 // support_g (5 x 128)
__device__ float  d_S2[FEW * G4];                // support_g @ W_hh[:,128:].T  (5 x 1024)
__device__ float  d_MS[D];                       // mean_support
__device__ float  d_q   [(size_t)NQ * D];        // gathered query embeddings (fp32)
__device__ __half d_q16 [(size_t)NQ * D];        // fp16 copy for GEMM A
__device__ __half d_hl16[(size_t)NQ * D];        // h_lstm[:, :128] fp16 (init: -q)
__device__ float  d_hl  [(size_t)NQ * D];        // fp32 hl (written only by last step)
__device__ float  d_Gbuf[(size_t)NQ * G4];       // G01 = q@(W_ih+W_hh[:,:128]).T + bsum
__device__ float  d_gates[(size_t)NQ * G4];      // per-step gates scratch
__device__ float  d_c   [(size_t)NQ * 256];      // LSTM cell state
__device__ float  d_attn[(size_t)NQ * 8];        // attention weights (5, padded to 8)
__device__ __half d_Wc16[G4 * D];                // W_ih + W_hh[:, :128] (fp16, packed 1024x128)
__device__ __half d_W116[G4 * D];                // W_hh[:, :128]        (fp16, packed 1024x128)
__device__ float  d_bsum[G4];                    // b_ih + b_hh

__device__ __forceinline__ float sigf(float x) { return 1.0f / (1.0f + expf(-x)); }

__device__ __forceinline__ void mma_f16(float* c, const unsigned* a, unsigned b0, unsigned b1) {
    asm volatile(
        "mma.sync.aligned.m16n8k16.row.col.f32.f16.f16.f32 "
        "{%0,%1,%2,%3}, {%4,%5,%6,%7}, {%8,%9}, {%0,%1,%2,%3};"
        : "+f"(c[0]), "+f"(c[1]), "+f"(c[2]), "+f"(c[3])
        : "r"(a[0]), "r"(a[1]), "r"(a[2]), "r"(a[3]), "r"(b0), "r"(b1));
}

// ---------------- tiny prep: fp16 weight packs / bsum ----------------
__global__ void k_wsum(const float* __restrict__ Wih, const float* __restrict__ Whh,
                       const float* __restrict__ bih, const float* __restrict__ bhh) {
    int idx = blockIdx.x * 256 + threadIdx.x;           // 1024*128 = 131072
    int r = idx >> 7, k = idx & 127;
    float w1 = Whh[(size_t)r * 256 + k];
    d_Wc16[idx] = __float2half_rn(Wih[idx] + w1);
    d_W116[idx] = __float2half_rn(w1);
    if (idx < 1024) d_bsum[idx] = bih[idx] + bhh[idx];
}

// ---------------- support path: GCN (linear!) + MLP + LayerNorm ----------------
__global__ void k_support(const int* __restrict__ sp, const float* __restrict__ emb,
                          const float* __restrict__ gW, const float* __restrict__ gb,
                          const float* __restrict__ p1W, const float* __restrict__ p1b,
                          const float* __restrict__ p2W, const float* __restrict__ p2b,
                          const float* __restrict__ lng, const float* __restrict__ lnb) {
    __shared__ float cs[256], s[128], h1[256], x[128], stat[2];
    int f = blockIdx.x, t = threadIdx.x;
    int side = t >> 7, col = t & 127;
    const int* pf = sp + f * 400;
    float acc = 0.f;
    #pragma unroll 4
    for (int n = 0; n < 200; n++) {
        int idx = pf[n * 2 + side];
        acc += emb[(size_t)idx * 128 + col];
    }
    cs[t] = acc;
    __syncthreads();
    if (t < 128) {                                   // support = tanh((csum@W.T + 200 b)/5)
        float a = 200.f * gb[t];
        #pragma unroll 4
        for (int k = 0; k < 256; k++) a = fmaf(cs[k], gW[t * 256 + k], a);
        s[t] = tanhf(a * 0.2f);
    }
    __syncthreads();
    {                                                // h1 = relu(s @ proj1_W.T + b1)
        float a = p1b[t];
        #pragma unroll 4
        for (int j = 0; j < 128; j++) a = fmaf(s[j], p1W[t * 128 + j], a);
        h1[t] = fmaxf(a, 0.f);
    }
    __syncthreads();
    if (t < 128) {                                   // x = h1 @ proj2_W.T + b2 + s
        float a = p2b[t];
        #pragma unroll 4
        for (int k = 0; k < 256; k++) a = fmaf(h1[k], p2W[t * 256 + k], a);
        x[t] = a + s[t];
    }
    __syncthreads();
    if (t == 0) {                                    // LayerNorm stats
        float mu = 0.f;
        for (int j = 0; j < 128; j++) mu += x[j];
        mu *= (1.f / 128.f);
        float v = 0.f;
        for (int j = 0; j < 128; j++) { float dd = x[j] - mu; v += dd * dd; }
        v *= (1.f / 128.f);
        stat[0] = mu; stat[1] = rsqrtf(v + 1e-5f);
    }
    __syncthreads();
    if (t < 128) d_SG[f * 128 + t] = lng[t] * (x[t] - stat[0]) * stat[1] + lnb[t];
}

// ---------------- S2 = SG @ W_hh[:,128:].T  and mean_support ----------------
__global__ void k_s2mean(const float* __restrict__ Whh) {
    __shared__ float sg[128];
    int b = blockIdx.x, t = threadIdx.x;             // block 128
    if (b < 40) {
        int f = b >> 3, gbk = b & 7;
        sg[t] = d_SG[f * 128 + t];
        __syncthreads();
        int g = gbk * 128 + t;
        float a = 0.f;
        #pragma unroll 4
        for (int j = 0; j < 128; j++) a = fmaf(sg[j], Whh[(size_t)g * 256 + 128 + j], a);
        d_S2[f * G4 + g] = a;
    } else {
        float a = 0.f;
        #pragma unroll
        for (int f = 0; f < FEW; f++) a += d_SG[f * 128 + t];
        d_MS[t] = a * 0.2f;
    }
}

// ---------------- gather q = emb[query_pairs]; q16; hl16 = -q (step-0 trick) ----------------
__global__ void k_gather(const int* __restrict__ qp, const float* __restrict__ emb) {
    int row = blockIdx.x * 8 + (threadIdx.x >> 5);
    int lane = threadIdx.x & 31;
    int idx = qp[row];
    float4 v = *(const float4*)(emb + (size_t)idx * 128 + lane * 4);
    *(float4*)(d_q + (size_t)row * 128 + lane * 4) = v;
    __half2 h0 = __floats2half2_rn(v.x, v.y);
    __half2 h1 = __floats2half2_rn(v.z, v.w);
    __half2 n0 = __floats2half2_rn(-v.x, -v.y);
    __half2 n1 = __floats2half2_rn(-v.z, -v.w);
    *(__half2*)(d_q16  + (size_t)row * 128 + lane * 4)     = h0;
    *(__half2*)(d_q16  + (size_t)row * 128 + lane * 4 + 2) = h1;
    *(__half2*)(d_hl16 + (size_t)row * 128 + lane * 4)     = n0;
    *(__half2*)(d_hl16 + (size_t)row * 128 + lane * 4 + 2) = n1;
}

// ---------------- fp16 tensor-core GEMM: 128(M) x 128(N), full K=128 in smem ----------------
// mode 0: Gbuf  = A @ B.T + bias              (A=q16,  B=Wc16)
// mode 1: gates = A @ B.T + Gbuf              (A=-q16, B=W116)   [step 0]
// mode 2: gates = A @ B.T + Gbuf + attn @ S2  (A=hl16, B=W116)
// last=1: BN block bx covers gate columns bx*256 .. bx*256+127, output packed width Nw.
__global__ void __launch_bounds__(256) k_gemm_fp16(const __half* __restrict__ A,
                                                   const __half* __restrict__ B,
                                                   int mode, int last, int Nw,
                                                   const float* __restrict__ bias) {
    extern __shared__ __half sm[];
    __half* As = sm;                    // 128 x SST
    __half* Bs = sm + 128 * SST;        // 128 x SST
    float* sS2   = (float*)sm;          // reused after MMA: 5 x 128
    float* sAttn = (float*)sm + FEW * 128; // 128 x 5

    int tid = threadIdx.x, lane = tid & 31, warp = tid >> 5;
    int g = lane >> 2, tg = lane & 3;
    int wm = warp >> 2, wn = warp & 3;          // 2(M) x 4(N); warp tile 64 x 32
    int bx = blockIdx.x, by = blockIdx.y;
    int colblk = bx * 128;
    int gb0 = last ? bx * 256 : colblk;
    const __half* Ag = A + (size_t)by * 128 * 128;
    const __half* Bg = B + (size_t)gb0 * 128;

    // ---- load tiles: 256 threads x 8 uint4 each ----
    #pragma unroll
    for (int it = 0; it < 8; it++) {
        int idx = tid + it * 256;                 // 0..2047 chunks of 8 halfs
        int r = idx >> 4, c8 = (idx & 15) << 3;
        *(uint4*)(As + r * SST + c8) = *(const uint4*)(Ag + r * 128 + c8);
        *(uint4*)(Bs + r * SST + c8) = *(const uint4*)(Bg + r * 128 + c8);
    }
    __syncthreads();

    float acc[4][4][4];
    #pragma unroll
    for (int mi = 0; mi < 4; mi++)
        #pragma unroll
        for (int ni = 0; ni < 4; ni++)
            #pragma unroll
            for (int r = 0; r < 4; r++) acc[mi][ni][r] = 0.f;

    #pragma unroll
    for (int kk = 0; kk < 8; kk++) {
        int c0 = kk * 16 + 2 * tg;
        unsigned a[4][4];
        #pragma unroll
        for (int mi = 0; mi < 4; mi++) {
            const __half* p = As + (wm * 64 + mi * 16 + g) * SST + c0;
            a[mi][0] = *(const unsigned*)(p);
            a[mi][1] = *(const unsigned*)(p + 8 * SST);
            a[mi][2] = *(const unsigned*)(p + 8);
            a[mi][3] = *(const unsigned*)(p + 8 * SST + 8);
        }
        #pragma unroll
        for (int ni = 0; ni < 4; ni++) {
            const __half* p = Bs + (wn * 32 + ni * 8 + g) * SST + c0;
            unsigned b0 = *(const unsigned*)(p);
            unsigned b1 = *(const unsigned*)(p + 8);
            #pragma unroll
            for (int mi = 0; mi < 4; mi++)
                mma_f16(acc[mi][ni], a[mi], b0, b1);
        }
    }

    if (mode == 2) {
        __syncthreads();                          // done reading As/Bs
        for (int i = tid; i < FEW * 128; i += 256)
            sS2[i] = d_S2[(i >> 7) * G4 + gb0 + (i & 127)];
        for (int i = tid; i < 128 * FEW; i += 256) {
            int r = i / FEW, f = i - r * FEW;
            sAttn[i] = d_attn[((size_t)(by * 128 + r)) * 8 + f];
        }
        __syncthreads();
    }

    // ---- epilogue ----
    #pragma unroll
    for (int mi = 0; mi < 4; mi++) {
        #pragma unroll
        for (int ni = 0; ni < 4; ni++) {
            int row0 = by * 128 + wm * 64 + mi * 16 + g;
            int cit = wn * 32 + ni * 8 + 2 * tg;
            if (mode == 0) {
                float2 bv = *(const float2*)(bias + colblk + cit);
                float2 o0 = make_float2(acc[mi][ni][0] + bv.x, acc[mi][ni][1] + bv.y);
                float2 o1 = make_float2(acc[mi][ni][2] + bv.x, acc[mi][ni][3] + bv.y);
                *(float2*)(d_Gbuf + (size_t)row0 * G4 + colblk + cit) = o0;
                *(float2*)(d_Gbuf + (size_t)(row0 + 8) * G4 + colblk + cit) = o1;
            } else {
                int gcol = gb0 + cit;
                #pragma unroll
                for (int rr = 0; rr < 2; rr++) {
                    int row = row0 + rr * 8;
                    float2 gv = *(const float2*)(d_Gbuf + (size_t)row * G4 + gcol);
                    float x0 = acc[mi][ni][rr * 2 + 0] + gv.x;
                    float x1 = acc[mi][ni][rr * 2 + 1] + gv.y;
                    if (mode == 2) {
                        int lr = row - by * 128;
                        #pragma unroll
                        for (int f = 0; f < FEW; f++) {
                            float av = sAttn[lr * FEW + f];
                            x0 = fmaf(av, sS2[f * 128 + cit], x0);
                            x1 = fmaf(av, sS2[f * 128 + cit + 1], x1);
                        }
                    }
                    *(float2*)(d_gates + (size_t)row * Nw + colblk + cit) = make_float2(x0, x1);
                }
            }
        }
    }
}

// ---------------- elementwise LSTM update + attention softmax ----------------
__global__ void __launch_bounds__(256) k_lstm(int first) {
    __shared__ float sSg[FEW * 128];
    for (int i = threadIdx.x; i < FEW * 128; i += 256) sSg[i] = d_SG[i];
    __syncthreads();
    int row = blockIdx.x * 8 + (threadIdx.x >> 5);
    int lane = threadIdx.x & 31;
    const float* gr = d_gates + (size_t)row * 1024;
    float part[FEW] = {0.f, 0.f, 0.f, 0.f, 0.f};
    #pragma unroll
    for (int k = 0; k < 8; k++) {
        int j = lane + 32 * k;
        float gi = gr[j], gf = gr[256 + j], gg = gr[512 + j], go = gr[768 + j];
        float co = first ? 0.f : d_c[(size_t)row * 256 + j];
        float cn = fmaf(sigf(gf), co, sigf(gi) * tanhf(gg));
        d_c[(size_t)row * 256 + j] = cn;
        if (k < 4) {
            float hl = sigf(go) * tanhf(cn);
            float hq = d_q[(size_t)row * 128 + j] + hl;
            d_hl16[(size_t)row * 128 + j] = __float2half_rn(hl);
            #pragma unroll
            for (int f = 0; f < FEW; f++) part[f] = fmaf(hq, sSg[f * 128 + j], part[f]);
        }
    }
    #pragma unroll
    for (int o = 16; o; o >>= 1)
        #pragma unroll
        for (int f = 0; f < FEW; f++) part[f] += __shfl_xor_sync(0xffffffffu, part[f], o);
    if (lane == 0) {
        float m = part[0];
        #pragma unroll
        for (int f = 1; f < FEW; f++) m = fmaxf(m, part[f]);
        float e[FEW], ss = 0.f;
        #pragma unroll
        for (int f = 0; f < FEW; f++) { e[f] = expf(part[f] - m); ss += e[f]; }
        float inv = 1.f / ss;
        #pragma unroll
        for (int f = 0; f < FEW; f++) d_attn[(size_t)row * 8 + f] = e[f] * inv;
    }
}

// last step: packed 512-wide gates, only c[:128]/hl needed; hl written fp32 for final
__global__ void __launch_bounds__(256) k_lstm_last() {
    int row = blockIdx.x * 8 + (threadIdx.x >> 5);
    int lane = threadIdx.x & 31;
    const float* gr = d_gates + (size_t)row * 512;
    #pragma unroll
    for (int k = 0; k < 4; k++) {
        int j = lane + 32 * k;
        float gi = gr[j], gf = gr[128 + j], gg = gr[256 + j], go = gr[384 + j];
        float co = d_c[(size_t)row * 256 + j];
        float cn = fmaf(sigf(gf), co, sigf(gi) * tanhf(gg));
        float hl = sigf(go) * tanhf(cn);
        d_hl[(size_t)row * 128 + j] = hl;
    }
}

// ---------------- final: out[b] = mean(hq[2b], hq[2b+1]) . mean_support ----------------
__global__ void k_final(float* __restrict__ out) {
    __shared__ float ms[128];
    int t = threadIdx.x;
    if (t < 128) ms[t] = d_MS[t];
    __syncthreads();
    int b = blockIdx.x * 8 + (t >> 5);
    int lane = t & 31;
    const float* q0 = d_q  + (size_t)b * 256;
    const float* h0 = d_hl + (size_t)b * 256;
    int j = lane * 4;
    float4 qa = *(const float4*)(q0 + j);
    float4 qb = *(const float4*)(q0 + 128 + j);
    float4 ha = *(const float4*)(h0 + j);
    float4 hb = *(const float4*)(h0 + 128 + j);
    float4 m4 = *(const float4*)(ms + j);
    float p = 0.5f * ((qa.x + ha.x + qb.x + hb.x) * m4.x +
                      (qa.y + ha.y + qb.y + hb.y) * m4.y +
                      (qa.z + ha.z + qb.z + hb.z) * m4.z +
                      (qa.w + ha.w + qb.w + hb.w) * m4.w);
    #pragma unroll
    for (int o = 16; o; o >>= 1) p += __shfl_xor_sync(0xffffffffu, p, o);
    if (lane == 0) out[b] = p;
}

// ---------------- launcher ----------------
extern "C" void kernel_launch(void* const* d_in, const int* in_sizes, int n_in,
                              void* d_out, int out_size) {
    const int*   qp  = (const int*)d_in[0];
    const int*   sp  = (const int*)d_in[1];
    const float* emb = (const float*)d_in[2];
    const float* gW  = (const float*)d_in[3];
    const float* gb  = (const float*)d_in[4];
    const float* p1W = (const float*)d_in[5];
    const float* p1b = (const float*)d_in[6];
    const float* p2W = (const float*)d_in[7];
    const float* p2b = (const float*)d_in[8];
    const float* lng = (const float*)d_in[9];
    const float* lnb = (const float*)d_in[10];
    const float* Wih = (const float*)d_in[11];
    const float* Whh = (const float*)d_in[12];
    const float* bih = (const float*)d_in[13];
    const float* bhh = (const float*)d_in[14];
    float* out = (float*)d_out;

    static int smem_set = 0;
    if (!smem_set) {
        cudaFuncSetAttribute(k_gemm_fp16, cudaFuncAttributeMaxDynamicSharedMemorySize, SMEM_BYTES);
        smem_set = 1;
    }

    k_wsum<<<512, 256>>>(Wih, Whh, bih, bhh);
    k_support<<<5, 256>>>(sp, emb, gW, gb, p1W, p1b, p2W, p2b, lng, lnb);
    k_s2mean<<<41, 128>>>(Whh);
    k_gather<<<NQ / 8, 256>>>(qp, emb);

    __half* pQ16;  cudaGetSymbolAddress((void**)&pQ16,  d_q16);
    __half* pHL16; cudaGetSymbolAddress((void**)&pHL16, d_hl16);
    __half* pWc;   cudaGetSymbolAddress((void**)&pWc,   d_Wc16);
    __half* pW1;   cudaGetSymbolAddress((void**)&pW1,   d_W116);
    float*  pBsum; cudaGetSymbolAddress((void**)&pBsum, d_bsum);

    dim3 gFull(8, NQ / 128);    // N = 1024
    dim3 gHalf(4, NQ / 128);    // N = 512 (last step, packed)

    // G01 precompute: Gbuf = q @ Wcomb.T + bsum
    k_gemm_fp16<<<gFull, 256, SMEM_BYTES>>>(pQ16, pWc, 0, 0, G4, pBsum);

    // step 0: gates = Gbuf + (-q) @ W1.T  (== q@Wih.T + b)
    k_gemm_fp16<<<gFull, 256, SMEM_BYTES>>>(pHL16, pW1, 1, 0, G4, pBsum);
    k_lstm<<<NQ / 8, 256>>>(1);

    // steps 1,2: gates = Gbuf + hl @ W1.T + attn @ S2
    for (int t = 0; t < 2; t++) {
        k_gemm_fp16<<<gFull, 256, SMEM_BYTES>>>(pHL16, pW1, 2, 0, G4, pBsum);
        k_lstm<<<NQ / 8, 256>>>(0);
    }

    // step 3: half the gate columns (packed 512), no attention afterwards
    k_gemm_fp16<<<gHalf, 256, SMEM_BYTES>>>(pHL16, pW1, 2, 1, 512, pBsum);
    k_lstm_last<<<NQ / 8, 256>>>();

    k_final<<<16384 / 8, 256>>>(out);
}